// round 5
// baseline (speedup 1.0000x reference)
#include <cuda_runtime.h>
#include <utility>

namespace cgk {

__host__ __device__ constexpr int my_abs(int x){ return x < 0 ? -x : x; }
__host__ __device__ constexpr int my_min(int a, int b){ return a < b ? a : b; }

// ---------------------------------------------------------------------------
// Compile-time tables replicating the reference's combo enumeration, the
// packed-C offsets, and the output layout (sorted (L,S) keys, blocks in
// combo insertion order, each block (2L+1) x 256 with M-stride = k*256).
// ---------------------------------------------------------------------------
struct Tab {
    int n;
    int l1[34], l2[34], L[34];
    int coff[34];   // offset of this combo's packed C slice in sC
    int obase[34];  // per-sample output base offset (key base + blk*256)
    int mstr[34];   // M stride within key = k*256
    int ctot;       // total packed C floats
    int outper;     // output floats per sample
};

__host__ __device__ constexpr Tab make_tab() {
    Tab t{};
    int n = 0;
    for (int a = 0; a < 4; ++a)
        for (int b = 0; b < 4; ++b)
            for (int L = my_abs(a - b); L <= my_min(a + b, 3); ++L) {
                t.l1[n] = a; t.l2[n] = b; t.L[n] = L; ++n;
            }
    t.n = n;
    int off = 0;
    for (int c = 0; c < n; ++c) {
        t.coff[c] = off;
        off += (2*t.l1[c]+1) * (2*t.l2[c]+1) * (2*t.L[c]+1);
    }
    t.ctot = off;
    int base = 0;
    for (int L = 0; L < 4; ++L)
        for (int si = 0; si < 2; ++si) {       // S = -1 then +1 (python tuple sort)
            int S = (si == 0) ? -1 : 1;
            int k = 0;
            for (int c = 0; c < n; ++c)
                if (t.L[c] == L && ((((t.l1[c]+t.l2[c]+L) & 1) ? -1 : 1) == S)) ++k;
            if (k == 0) continue;
            int blk = 0;
            for (int c = 0; c < n; ++c)
                if (t.L[c] == L && ((((t.l1[c]+t.l2[c]+L) & 1) ? -1 : 1) == S)) {
                    t.obase[c] = base + blk * 256;
                    t.mstr[c]  = k * 256;
                    ++blk;
                }
            base += (2*L+1) * k * 256;
        }
    t.outper = base;
    return t;
}

constexpr Tab TB = make_tab();
constexpr int NC      = 34;
constexpr int CSZ     = TB.ctot;     // 3436
constexpr int OUT_PER = TB.outper;   // 39936
constexpr int SPB = 8;               // samples per block
constexpr int TPB = 128;             // threads per block (16 p-lanes x 8 samples)
constexpr int NSAMP = 4000;

static_assert(TB.n == 34, "combo count");
static_assert(CSZ == 3436, "packed C size");
static_assert(OUT_PER == 39936, "output width");

// cg_coeffs strides for shape (4,4,4,7,7,7)
constexpr int CG_SL1 = 4*4*7*7*7;  // 5488
constexpr int CG_SL2 = 4*7*7*7;    // 1372
constexpr int CG_SL  = 7*7*7;      // 343
constexpr int CG_SI  = 49;
constexpr int CG_SJ  = 7;

// ---------------------------------------------------------------------------
// Pack the needed C slices into shared memory.
// ---------------------------------------------------------------------------
template<int C>
__device__ __forceinline__ void load_c(const float* __restrict__ cg,
                                       float* __restrict__ sC, int tid)
{
    constexpr int l1 = TB.l1[C], l2 = TB.l2[C], L = TB.L[C];
    constexpr int D1 = 2*l1+1, D2 = 2*l2+1, DM = 2*L+1;
    constexpr int SZ = D1 * D2 * DM;
    constexpr int CO = TB.coff[C];
    const float* src = cg + l1*CG_SL1 + l2*CG_SL2 + L*CG_SL;
    for (int k = tid; k < SZ; k += TPB) {
        int i = k / (D2 * DM);
        int r = k - i * (D2 * DM);
        int j = r / DM;
        int M = r - j * DM;
        sC[CO + k] = src[i*CG_SI + j*CG_SJ + M];
    }
}

template<int... Cs>
__device__ __forceinline__ void load_c_all(std::integer_sequence<int, Cs...>,
                                           const float* __restrict__ cg,
                                           float* __restrict__ sC, int tid)
{
    (load_c<Cs>(cg, sC, tid), ...);
}

// ---------------------------------------------------------------------------
// One combo, one (sample, p) thread:
//   stage 1: t[j,M] = sum_i x1[i,p] * C[i,j,M]      (C broadcast from smem)
//   stage 2: out[M, p, q] = sum_j t[j,M] * x2[j,q]  (x2 float4 from smem)
// ---------------------------------------------------------------------------
template<int C>
__device__ __forceinline__ void do_combo(const float* __restrict__ sC,
                                         const float (&sX2)[SPB][16][16],
                                         int s, int p,
                                         const float (&x1r)[16],
                                         float* __restrict__ outp)
{
    constexpr int l1 = TB.l1[C], l2 = TB.l2[C], L = TB.L[C];
    constexpr int D1 = 2*l1+1, D2 = 2*l2+1, DM = 2*L+1;
    constexpr int CO  = TB.coff[C];
    constexpr int OB  = TB.obase[C];
    constexpr int MS  = TB.mstr[C];
    constexpr int X1O = l1 * l1;   // row offset of l1 block {0,1,4,9}
    constexpr int X2O = l2 * l2;   // row offset of l2 block {0,1,4,9}

    float t[D2 * DM];
#pragma unroll
    for (int i = 0; i < D1; ++i) {
        const float a = x1r[X1O + i];
#pragma unroll
        for (int j = 0; j < D2; ++j) {
#pragma unroll
            for (int M = 0; M < DM; ++M) {
                const float cc = sC[CO + (i*D2 + j)*DM + M];
                if (i == 0) t[j*DM + M] = a * cc;
                else        t[j*DM + M] = fmaf(a, cc, t[j*DM + M]);
            }
        }
    }

#pragma unroll
    for (int qq = 0; qq < 4; ++qq) {
        float4 acc[DM];
#pragma unroll
        for (int j = 0; j < D2; ++j) {
            const float4 v =
                *reinterpret_cast<const float4*>(&sX2[s][X2O + j][qq * 4]);
#pragma unroll
            for (int M = 0; M < DM; ++M) {
                const float tv = t[j*DM + M];
                if (j == 0) {
                    acc[M].x = tv * v.x; acc[M].y = tv * v.y;
                    acc[M].z = tv * v.z; acc[M].w = tv * v.w;
                } else {
                    acc[M].x = fmaf(tv, v.x, acc[M].x);
                    acc[M].y = fmaf(tv, v.y, acc[M].y);
                    acc[M].z = fmaf(tv, v.z, acc[M].z);
                    acc[M].w = fmaf(tv, v.w, acc[M].w);
                }
            }
        }
#pragma unroll
        for (int M = 0; M < DM; ++M) {
            __stcs(reinterpret_cast<float4*>(outp + OB + M*MS + p*16 + qq*4),
                   acc[M]);
        }
    }
}

template<int... Cs>
__device__ __forceinline__ void do_all(std::integer_sequence<int, Cs...>,
                                       const float* __restrict__ sC,
                                       const float (&sX2)[SPB][16][16],
                                       int s, int p,
                                       const float (&x1r)[16],
                                       float* __restrict__ outp)
{
    (do_combo<Cs>(sC, sX2, s, p, x1r, outp), ...);
}

// ---------------------------------------------------------------------------
// Kernel: 128 threads = 8 samples x 16 p-lanes. Warp = 2 samples.
// ---------------------------------------------------------------------------
__global__ void __launch_bounds__(TPB, 3) cg_kernel(
    const float* __restrict__ x10, const float* __restrict__ x11,
    const float* __restrict__ x12, const float* __restrict__ x13,
    const float* __restrict__ x20, const float* __restrict__ x21,
    const float* __restrict__ x22, const float* __restrict__ x23,
    const float* __restrict__ cg,  float* __restrict__ out)
{
    __shared__ __align__(16) float sC[CSZ];
    __shared__ __align__(16) float sX2[SPB][16][16];

    const int tid = threadIdx.x;
    const int bs  = blockIdx.x * SPB;

    // Pack C slices (broadcast-read later).
    load_c_all(std::make_integer_sequence<int, NC>{}, cg, sC, tid);

    // Stage x2 for the 8 samples: sX2[s][row(l2,j)][q], q contiguous.
    {
        const float* x2p[4] = {x20, x21, x22, x23};
#pragma unroll
        for (int l = 0; l < 4; ++l) {
            const int D = 2*l + 1;
            const int base_row = l * l;
            const float* src = x2p[l] + bs * D * 16;
            for (int k = tid; k < SPB * D * 16; k += TPB) {
                int s = k / (D * 16);
                int r = k - s * (D * 16);
                sX2[s][base_row + (r >> 4)][r & 15] = src[k];
            }
        }
    }

    // x1 for this thread's (sample, p) into registers.
    const int s = tid >> 4;
    const int p = tid & 15;
    const int n = bs + s;
    float x1r[16];
    {
        const float* x1p[4] = {x10, x11, x12, x13};
#pragma unroll
        for (int l = 0; l < 4; ++l) {
            const int base_row = l * l;
#pragma unroll
            for (int i = 0; i < 2*l + 1; ++i)
                x1r[base_row + i] = x1p[l][(n * (2*l + 1) + i) * 16 + p];
        }
    }

    __syncthreads();

    float* outp = out + (long long)n * OUT_PER;
    do_all(std::make_integer_sequence<int, NC>{}, sC, sX2, s, p, x1r, outp);
}

} // namespace cgk

extern "C" void kernel_launch(void* const* d_in, const int* in_sizes, int n_in,
                              void* d_out, int out_size)
{
    (void)out_size;
    // Identify inputs by element count, robust to metadata ordering
    // (setup_inputs inserts interleaved: x1_l0, x2_l0, x1_l1, x2_l1, ..., cg).
    // Sizes: l=0 -> 64000, l=1 -> 192000, l=2 -> 320000, l=3 -> 448000,
    // cg_coeffs -> 21952. Within each l, x1 appears before x2.
    const float* x1p[4] = {nullptr, nullptr, nullptr, nullptr};
    const float* x2p[4] = {nullptr, nullptr, nullptr, nullptr};
    const float* cg = nullptr;
    for (int i = 0; i < n_in; ++i) {
        const int sz = in_sizes[i];
        const float* ptr = (const float*)d_in[i];
        if (sz == 21952) { cg = ptr; continue; }
        int l = -1;
        if      (sz ==  64000) l = 0;
        else if (sz == 192000) l = 1;
        else if (sz == 320000) l = 2;
        else if (sz == 448000) l = 3;
        if (l >= 0) {
            if (!x1p[l]) x1p[l] = ptr;      // first occurrence = x1_l
            else         x2p[l] = ptr;      // second occurrence = x2_l
        }
    }

    cgk::cg_kernel<<<cgk::NSAMP / cgk::SPB, cgk::TPB>>>(
        x1p[0], x1p[1], x1p[2], x1p[3],
        x2p[0], x2p[1], x2p[2], x2p[3],
        cg, (float*)d_out);
}

// round 6
// speedup vs baseline: 3.9876x; 3.9876x over previous
#include <cuda_runtime.h>
#include <utility>

namespace cgk {

__host__ __device__ constexpr int my_abs(int x){ return x < 0 ? -x : x; }
__host__ __device__ constexpr int my_min(int a, int b){ return a < b ? a : b; }

// ---------------------------------------------------------------------------
// Compile-time tables replicating the reference's combo enumeration, the
// packed-C offsets, and the output layout (sorted (L,S) keys, blocks in
// combo insertion order, each block (2L+1) x 256 with M-stride = k*256).
// ---------------------------------------------------------------------------
struct Tab {
    int n;
    int l1[34], l2[34], L[34];
    int coff[34];   // offset of this combo's packed C slice in sC
    int obase[34];  // per-sample output base offset (key base + blk*256)
    int mstr[34];   // M stride within key = k*256
    int ctot;       // total packed C floats
    int outper;     // output floats per sample
};

__host__ __device__ constexpr Tab make_tab() {
    Tab t{};
    int n = 0;
    for (int a = 0; a < 4; ++a)
        for (int b = 0; b < 4; ++b)
            for (int L = my_abs(a - b); L <= my_min(a + b, 3); ++L) {
                t.l1[n] = a; t.l2[n] = b; t.L[n] = L; ++n;
            }
    t.n = n;
    int off = 0;
    for (int c = 0; c < n; ++c) {
        t.coff[c] = off;
        off += (2*t.l1[c]+1) * (2*t.l2[c]+1) * (2*t.L[c]+1);
    }
    t.ctot = off;
    int base = 0;
    for (int L = 0; L < 4; ++L)
        for (int si = 0; si < 2; ++si) {       // S = -1 then +1 (python tuple sort)
            int S = (si == 0) ? -1 : 1;
            int k = 0;
            for (int c = 0; c < n; ++c)
                if (t.L[c] == L && ((((t.l1[c]+t.l2[c]+L) & 1) ? -1 : 1) == S)) ++k;
            if (k == 0) continue;
            int blk = 0;
            for (int c = 0; c < n; ++c)
                if (t.L[c] == L && ((((t.l1[c]+t.l2[c]+L) & 1) ? -1 : 1) == S)) {
                    t.obase[c] = base + blk * 256;
                    t.mstr[c]  = k * 256;
                    ++blk;
                }
            base += (2*L+1) * k * 256;
        }
    t.outper = base;
    return t;
}

constexpr Tab TB = make_tab();
constexpr int NC      = 34;
constexpr int CSZ     = TB.ctot;     // 3436
constexpr int OUT_PER = TB.outper;   // 39936
constexpr int SPB = 4;               // samples per block
constexpr int TPB = 256;             // 4 samples x 16 p x 4 qq
constexpr int NSAMP = 4000;

static_assert(TB.n == 34, "combo count");
static_assert(CSZ == 3436, "packed C size");
static_assert(OUT_PER == 39936, "output width");

// cg_coeffs strides for shape (4,4,4,7,7,7)
constexpr int CG_SL1 = 4*4*7*7*7;  // 5488
constexpr int CG_SL2 = 4*7*7*7;    // 1372
constexpr int CG_SL  = 7*7*7;      // 343
constexpr int CG_SI  = 49;
constexpr int CG_SJ  = 7;

// ---------------------------------------------------------------------------
// Pack the needed C slices into shared memory.
// ---------------------------------------------------------------------------
template<int C>
__device__ __forceinline__ void load_c(const float* __restrict__ cg,
                                       float* __restrict__ sC, int tid)
{
    constexpr int l1 = TB.l1[C], l2 = TB.l2[C], L = TB.L[C];
    constexpr int D1 = 2*l1+1, D2 = 2*l2+1, DM = 2*L+1;
    constexpr int SZ = D1 * D2 * DM;
    constexpr int CO = TB.coff[C];
    const float* src = cg + l1*CG_SL1 + l2*CG_SL2 + L*CG_SL;
    for (int k = tid; k < SZ; k += TPB) {
        int i = k / (D2 * DM);
        int r = k - i * (D2 * DM);
        int j = r / DM;
        int M = r - j * DM;
        sC[CO + k] = src[i*CG_SI + j*CG_SJ + M];
    }
}

template<int... Cs>
__device__ __forceinline__ void load_c_all(std::integer_sequence<int, Cs...>,
                                           const float* __restrict__ cg,
                                           float* __restrict__ sC, int tid)
{
    (load_c<Cs>(cg, sC, tid), ...);
}

// ---------------------------------------------------------------------------
// One combo, one (sample, p, qq) thread:
//   stage 1: t[j,M] = sum_i x1[i,p] * C[i,j,M]      (C broadcast from smem)
//   stage 2: out[M, p, qq*4..qq*4+3] = sum_j t[j,M] * x2[j, qq*4..]
// ---------------------------------------------------------------------------
template<int C>
__device__ __forceinline__ void do_combo(const float* __restrict__ sC,
                                         const float (&sX2)[SPB][16][16],
                                         int s, int p, int qq,
                                         const float (&x1r)[16],
                                         float* __restrict__ outp)
{
    constexpr int l1 = TB.l1[C], l2 = TB.l2[C], L = TB.L[C];
    constexpr int D1 = 2*l1+1, D2 = 2*l2+1, DM = 2*L+1;
    constexpr int CO  = TB.coff[C];
    constexpr int OB  = TB.obase[C];
    constexpr int MS  = TB.mstr[C];
    constexpr int X1O = l1 * l1;   // row offset of l1 block {0,1,4,9}
    constexpr int X2O = l2 * l2;   // row offset of l2 block {0,1,4,9}

    float t[D2 * DM];
#pragma unroll
    for (int i = 0; i < D1; ++i) {
        const float a = x1r[X1O + i];
#pragma unroll
        for (int j = 0; j < D2; ++j) {
#pragma unroll
            for (int M = 0; M < DM; ++M) {
                const float cc = sC[CO + (i*D2 + j)*DM + M];
                if (i == 0) t[j*DM + M] = a * cc;
                else        t[j*DM + M] = fmaf(a, cc, t[j*DM + M]);
            }
        }
    }

    float4 acc[DM];
#pragma unroll
    for (int j = 0; j < D2; ++j) {
        const float4 v =
            *reinterpret_cast<const float4*>(&sX2[s][X2O + j][qq * 4]);
#pragma unroll
        for (int M = 0; M < DM; ++M) {
            const float tv = t[j*DM + M];
            if (j == 0) {
                acc[M].x = tv * v.x; acc[M].y = tv * v.y;
                acc[M].z = tv * v.z; acc[M].w = tv * v.w;
            } else {
                acc[M].x = fmaf(tv, v.x, acc[M].x);
                acc[M].y = fmaf(tv, v.y, acc[M].y);
                acc[M].z = fmaf(tv, v.z, acc[M].z);
                acc[M].w = fmaf(tv, v.w, acc[M].w);
            }
        }
    }
#pragma unroll
    for (int M = 0; M < DM; ++M) {
        __stcs(reinterpret_cast<float4*>(outp + OB + M*MS + p*16 + qq*4),
               acc[M]);
    }
}

template<int... Cs>
__device__ __forceinline__ void do_all(std::integer_sequence<int, Cs...>,
                                       const float* __restrict__ sC,
                                       const float (&sX2)[SPB][16][16],
                                       int s, int p, int qq,
                                       const float (&x1r)[16],
                                       float* __restrict__ outp)
{
    (do_combo<Cs>(sC, sX2, s, p, qq, x1r, outp), ...);
}

// ---------------------------------------------------------------------------
// Kernel: 256 threads = 4 samples x 16 p x 4 qq.
// Warp = 1 sample x 8 p x 4 qq -> per-M stores are 512B contiguous per warp.
// ---------------------------------------------------------------------------
__global__ void __launch_bounds__(TPB, 2) cg_kernel(
    const float* __restrict__ x10, const float* __restrict__ x11,
    const float* __restrict__ x12, const float* __restrict__ x13,
    const float* __restrict__ x20, const float* __restrict__ x21,
    const float* __restrict__ x22, const float* __restrict__ x23,
    const float* __restrict__ cg,  float* __restrict__ out)
{
    __shared__ __align__(16) float sC[CSZ];
    __shared__ __align__(16) float sX2[SPB][16][16];

    const int tid = threadIdx.x;
    const int bs  = blockIdx.x * SPB;

    // Pack C slices (broadcast-read later).
    load_c_all(std::make_integer_sequence<int, NC>{}, cg, sC, tid);

    // Stage x2 for the 4 samples: sX2[s][row(l2,j)][q], q contiguous.
    {
        const float* x2p[4] = {x20, x21, x22, x23};
#pragma unroll
        for (int l = 0; l < 4; ++l) {
            const int D = 2*l + 1;
            const int base_row = l * l;
            const float* src = x2p[l] + bs * D * 16;
            for (int k = tid; k < SPB * D * 16; k += TPB) {
                int s = k / (D * 16);
                int r = k - s * (D * 16);
                sX2[s][base_row + (r >> 4)][r & 15] = src[k];
            }
        }
    }

    // Thread mapping: qq fastest, then p, then sample.
    const int qq = tid & 3;
    const int p  = (tid >> 2) & 15;
    const int s  = tid >> 6;
    const int n  = bs + s;

    // x1 for this thread's (sample, p) into registers.
    float x1r[16];
    {
        const float* x1p[4] = {x10, x11, x12, x13};
#pragma unroll
        for (int l = 0; l < 4; ++l) {
            const int base_row = l * l;
#pragma unroll
            for (int i = 0; i < 2*l + 1; ++i)
                x1r[base_row + i] = x1p[l][(n * (2*l + 1) + i) * 16 + p];
        }
    }

    __syncthreads();

    float* outp = out + (long long)n * OUT_PER;
    do_all(std::make_integer_sequence<int, NC>{}, sC, sX2, s, p, qq, x1r, outp);
}

} // namespace cgk

extern "C" void kernel_launch(void* const* d_in, const int* in_sizes, int n_in,
                              void* d_out, int out_size)
{
    (void)out_size;
    // Identify inputs by element count, robust to metadata ordering
    // (setup_inputs inserts interleaved: x1_l0, x2_l0, x1_l1, x2_l1, ..., cg).
    // Sizes: l=0 -> 64000, l=1 -> 192000, l=2 -> 320000, l=3 -> 448000,
    // cg_coeffs -> 21952. Within each l, x1 appears before x2.
    const float* x1p[4] = {nullptr, nullptr, nullptr, nullptr};
    const float* x2p[4] = {nullptr, nullptr, nullptr, nullptr};
    const float* cg = nullptr;
    for (int i = 0; i < n_in; ++i) {
        const int sz = in_sizes[i];
        const float* ptr = (const float*)d_in[i];
        if (sz == 21952) { cg = ptr; continue; }
        int l = -1;
        if      (sz ==  64000) l = 0;
        else if (sz == 192000) l = 1;
        else if (sz == 320000) l = 2;
        else if (sz == 448000) l = 3;
        if (l >= 0) {
            if (!x1p[l]) x1p[l] = ptr;      // first occurrence = x1_l
            else         x2p[l] = ptr;      // second occurrence = x2_l
        }
    }

    cgk::cg_kernel<<<cgk::NSAMP / cgk::SPB, cgk::TPB>>>(
        x1p[0], x1p[1], x1p[2], x1p[3],
        x2p[0], x2p[1], x2p[2], x2p[3],
        cg, (float*)d_out);
}